// round 10
// baseline (speedup 1.0000x reference)
#include <cuda_runtime.h>
#include <cuda_fp16.h>
#include <math.h>

#define N_NODES 50000
#define D 100
#define DPH 104   // half-slots per node: 100 fp16 premult feats + fp32 w (2 slots) + 2 pad
#define E_EDGES 800000
#define OUTD 300

// Scratch (allocation-free). Row c of g_hgw[b]: halves 0..99 = fp16(w_c * f_c[j]),
// slots 100..101 hold w_c as one fp32 word, 102..103 pad.
// w = exp(score), score in [-1,1] so exp never overflows and the reference's
// max-subtraction cancels exactly in the softmax ratio.
__device__ __align__(16) __half g_hgw[2][(size_t)N_NODES * DPH];
__device__ __align__(16) float g_nr[128];
__device__ __align__(16) int g_coff[E_EDGES + 32];
__device__ int g_rowptr[N_NODES + 1];

typedef unsigned long long u64;

// ---------------------------------------------------------------------------
__device__ __forceinline__ void fadd2(u64& a, u64 b) {
    asm("add.rn.f32x2 %0, %0, %1;" : "+l"(a) : "l"(b));
}
__device__ __forceinline__ float2 unpack2(u64 v) {
    float2 r;
    asm("mov.b64 {%0, %1}, %2;" : "=f"(r.x), "=f"(r.y) : "l"(v));
    return r;
}
__device__ __forceinline__ u64 pack2(float x, float y) {
    u64 r;
    asm("mov.b64 %0, {%1, %2};" : "=l"(r) : "f"(x), "f"(y));
    return r;
}
__device__ __forceinline__ u64 h2f2(unsigned int h) {   // half2 -> packed f32x2
    __half2 hv = *(__half2*)&h;
    float2 f = __half22float2(hv);
    return pack2(f.x, f.y);
}
__device__ __forceinline__ float tanha(float x) {       // HW tanh approx
    float r;
    asm("tanh.approx.f32 %0, %1;" : "=f"(r) : "f"(x));
    return r;
}

// ---------------------------------------------------------------------------
// Prep: packed col half-offsets + CSR row pointers (rows sorted; binary search).
// Block 0 threads 0..127 additionally build the normalized none_relation.
__global__ void prep_kernel(const int* __restrict__ adj,
                            const float* __restrict__ none_rel) {
    if (blockIdx.x == 0 && threadIdx.x < 128) {
        __shared__ float ssum[128];
        int t = threadIdx.x;
        float v = (t < D) ? none_rel[t] : 0.f;
        ssum[t] = v * v;
        __syncthreads();
        for (int s = 64; s > 0; s >>= 1) {
            if (t < s) ssum[t] += ssum[t + s];
            __syncthreads();
        }
        float inv = 1.f / fmaxf(sqrtf(ssum[0]), 1e-12f);
        g_nr[t] = (t < D) ? v * inv : 0.f;
    }
    int i = blockIdx.x * blockDim.x + threadIdx.x;
    if (i < E_EDGES)
        g_coff[i] = adj[2 * i + 1] * DPH;
    if (i <= N_NODES) {
        int lo = 0, hi = E_EDGES;
        while (lo < hi) {
            int mid = (lo + hi) >> 1;
            if (adj[2 * mid] < i) lo = mid + 1; else hi = mid;
        }
        g_rowptr[i] = lo;
    }
}

// ---------------------------------------------------------------------------
// Warp-collective epilogue: r = fp32 feature chunk f[4l..4l+3] on lanes 0..24.
// Compute w = exp(-dot(l2norm(r), nr)); store fp16 premult row + fp32 w.
__device__ __forceinline__ void epilogue_store(float4 r, int lane, int node, int fbuf) {
    float dot = 0.f, ss = 0.f;
    if (lane < 25) {
        float4 nv = *(const float4*)(g_nr + lane * 4);
        dot = r.x * nv.x + r.y * nv.y + r.z * nv.z + r.w * nv.w;
        ss  = r.x * r.x + r.y * r.y + r.z * r.z + r.w * r.w;
    }
    #pragma unroll
    for (int o = 16; o; o >>= 1) {
        dot += __shfl_xor_sync(0xffffffffu, dot, o);
        ss  += __shfl_xor_sync(0xffffffffu, ss, o);
    }
    float w = __expf(-dot / fmaxf(sqrtf(ss), 1e-12f));
    __half* dst = g_hgw[fbuf] + (size_t)node * DPH;
    if (lane < 25) {
        __half2 h0 = __floats2half2_rn(w * r.x, w * r.y);
        __half2 h1 = __floats2half2_rn(w * r.z, w * r.w);
        uint2 p;
        p.x = *(unsigned int*)&h0;
        p.y = *(unsigned int*)&h1;
        *(uint2*)(dst + lane * 4) = p;
    } else if (lane == 25) {
        uint2 p;
        p.x = __float_as_uint(w);
        p.y = 0u;
        *(uint2*)(dst + 100) = p;
    }
}

// ---------------------------------------------------------------------------
// Layer 0: r = tanh(features); write out cols [0,D), build g_hgw[0].
__global__ void tanh_score_kernel(const float* __restrict__ feat,
                                  float* __restrict__ out) {
    int node = (blockIdx.x * blockDim.x + threadIdx.x) >> 5;
    int lane = threadIdx.x & 31;
    if (node >= N_NODES) return;
    float4 r = make_float4(0.f, 0.f, 0.f, 0.f);
    if (lane < 25) {
        float4 v = *(const float4*)(feat + (size_t)node * D + lane * 4);
        r.x = tanha(v.x); r.y = tanha(v.y); r.z = tanha(v.z); r.w = tanha(v.w);
        *(float4*)(out + (size_t)node * OUTD + lane * 4) = r;
    }
    epilogue_store(r, lane, node, 0);
}

// ---------------------------------------------------------------------------
// Attention row kernel: gather-sum of fp16 premultiplied rows.
// Lanes 0..12 each load 16B (8 halves); lane 12's .z word is the fp32 w.
// a0..a3 accumulate f[8l..8l+7] as packed f32x2; lane12 a2.x accumulates den.
template <bool LAST>
__global__ void __launch_bounds__(256) row_kernel(int buf, float* __restrict__ out,
                                                  int outoff) {
    int row = (blockIdx.x * blockDim.x + threadIdx.x) >> 5;
    int lane = threadIdx.x & 31;
    if (row >= N_NODES) return;
    int beg = g_rowptr[row];
    int end = g_rowptr[row + 1];
    const __half* __restrict__ hgw = g_hgw[buf];
    bool wlane = (lane == 12);

    u64 a0 = 0ull, a1 = 0ull, a2 = 0ull, a3 = 0ull;

#define EDGE(off) do {                                                        \
        if (lane < 13) {                                                      \
            uint4 v = *(const uint4*)(hgw + (off) + lane * 8);                \
            fadd2(a0, h2f2(v.x));                                             \
            fadd2(a1, h2f2(v.y));                                             \
            fadd2(a2, wlane ? (u64)v.z : h2f2(v.z));                          \
            fadd2(a3, wlane ? 0ull : h2f2(v.w));                              \
        } } while (0)

    int e = beg;
    int cnt = end - beg;
    int pre = (4 - (beg & 3)) & 3;
    if (pre > cnt) pre = cnt;
    for (int k = 0; k < pre; ++k, ++e) { int o = g_coff[e]; EDGE(o); }
    for (; e + 16 <= end; e += 16) {
        int4 q0 = *(const int4*)(g_coff + e);
        int4 q1 = *(const int4*)(g_coff + e + 4);
        int4 q2 = *(const int4*)(g_coff + e + 8);
        int4 q3 = *(const int4*)(g_coff + e + 12);
        EDGE(q0.x); EDGE(q0.y); EDGE(q0.z); EDGE(q0.w);
        EDGE(q1.x); EDGE(q1.y); EDGE(q1.z); EDGE(q1.w);
        EDGE(q2.x); EDGE(q2.y); EDGE(q2.z); EDGE(q2.w);
        EDGE(q3.x); EDGE(q3.y); EDGE(q3.z); EDGE(q3.w);
    }
    for (; e + 4 <= end; e += 4) {
        int4 q = *(const int4*)(g_coff + e);
        EDGE(q.x); EDGE(q.y); EDGE(q.z); EDGE(q.w);
    }
    for (; e < end; ++e) { int o = g_coff[e]; EDGE(o); }
#undef EDGE

    float den = __shfl_sync(0xffffffffu, unpack2(a2).x, 12);
    float inv = (end > beg) ? (1.f / den) : 0.f;

    // Redistribute: lane t wants f[4t..4t+3]; source lane s = t>>1 holds
    // f[8s..8s+7] in (a0,a1,a2,a3). Even t -> (a0,a1); odd t -> (a2,a3).
    int src = lane >> 1;
    u64 b0 = __shfl_sync(0xffffffffu, a0, src);
    u64 b1 = __shfl_sync(0xffffffffu, a1, src);
    u64 b2 = __shfl_sync(0xffffffffu, a2, src);
    u64 b3 = __shfl_sync(0xffffffffu, a3, src);
    u64 plo = (lane & 1) ? b2 : b0;
    u64 phi = (lane & 1) ? b3 : b1;
    float2 fl = unpack2(plo);
    float2 fh = unpack2(phi);

    float4 r;
    r.x = tanha(fl.x * inv);
    r.y = tanha(fl.y * inv);
    r.z = tanha(fh.x * inv);
    r.w = tanha(fh.y * inv);
    if (lane < 25)
        *(float4*)(out + (size_t)row * OUTD + outoff + lane * 4) = r;
    if (!LAST)
        epilogue_store(r, lane, row, buf ^ 1);
}

// ---------------------------------------------------------------------------
extern "C" void kernel_launch(void* const* d_in, const int* in_sizes, int n_in,
                              void* d_out, int out_size) {
    const float* features = (const float*)d_in[0];
    // d_in[1] = rel_emb: unused by the reference computation.
    const int* adj        = (const int*)d_in[2];   // int32 pairs (JAX demotes int64)
    const float* none_rel = (const float*)d_in[3];
    float* out = (float*)d_out;

    const int WPB = 256;
    const int NODE_BLOCKS = (N_NODES * 32 + WPB - 1) / WPB;

    prep_kernel<<<(E_EDGES + 255) / 256, 256>>>(adj, none_rel);
    tanh_score_kernel<<<NODE_BLOCKS, WPB>>>(features, out);
    row_kernel<false><<<NODE_BLOCKS, WPB>>>(0, out, D);
    row_kernel<true ><<<NODE_BLOCKS, WPB>>>(1, out, 2 * D);
}

// round 11
// speedup vs baseline: 1.1837x; 1.1837x over previous
#include <cuda_runtime.h>
#include <math.h>

#define N_NODES 50000
#define D 100
#define DP 104                 // padded row: 100 premultiplied feats + w + 3 pad
#define E_EDGES 800000
#define OUTD 300

// Scratch (allocation-free). g_gw[b][node*DP..] = [w*f[0..99], w, 0,0,0].
// w[c] = exp(score[c]); score in [-1,1] so exp never overflows and the
// reference's max-subtraction cancels exactly in the softmax ratio.
__device__ __align__(16) float g_gw[2][(size_t)N_NODES * DP + 32];
__device__ __align__(16) float g_nr[128];
__device__ __align__(16) int g_coff[E_EDGES + 32];
__device__ int g_rowptr[N_NODES + 1];

typedef unsigned long long u64;

// ---------------------------------------------------------------------------
__device__ __forceinline__ void fadd2(u64& a, u64 b) {
    asm("add.rn.f32x2 %0, %0, %1;" : "+l"(a) : "l"(b));
}
__device__ __forceinline__ float2 unpack2(u64 v) {
    float2 r;
    asm("mov.b64 {%0, %1}, %2;" : "=f"(r.x), "=f"(r.y) : "l"(v));
    return r;
}
__device__ __forceinline__ float tanha(float x) {      // HW tanh approx
    float r;
    asm("tanh.approx.f32 %0, %1;" : "=f"(r) : "f"(x));
    return r;
}

// ---------------------------------------------------------------------------
// Prep: packed col offsets + CSR row pointers (rows sorted; binary search).
// Block 0 threads 0..127 additionally build the normalized none_relation.
__global__ void prep_kernel(const int* __restrict__ adj,
                            const float* __restrict__ none_rel) {
    if (blockIdx.x == 0 && threadIdx.x < 128) {
        __shared__ float ssum[128];
        int t = threadIdx.x;
        float v = (t < D) ? none_rel[t] : 0.f;
        ssum[t] = v * v;
        __syncthreads();
        for (int s = 64; s > 0; s >>= 1) {
            if (t < s) ssum[t] += ssum[t + s];
            __syncthreads();
        }
        float inv = 1.f / fmaxf(sqrtf(ssum[0]), 1e-12f);
        g_nr[t] = (t < D) ? v * inv : 0.f;
    }
    int i = blockIdx.x * blockDim.x + threadIdx.x;
    if (i < E_EDGES)
        g_coff[i] = adj[2 * i + 1] * DP;
    if (i <= N_NODES) {
        int lo = 0, hi = E_EDGES;
        while (lo < hi) {
            int mid = (lo + hi) >> 1;
            if (adj[2 * mid] < i) lo = mid + 1; else hi = mid;
        }
        g_rowptr[i] = lo;
    }
}

// ---------------------------------------------------------------------------
// Warp-collective epilogue: from this node's fp32 feature chunk r (lanes 0..24),
// compute w = exp(-dot(l2norm(r), nr)); store [w*r, w, 0,0,0] into g_gw[fbuf].
__device__ __forceinline__ void epilogue_store(float4 r, int lane, int node, int fbuf) {
    float dot = 0.f, ss = 0.f;
    if (lane < 25) {
        float4 nv = *(const float4*)(g_nr + lane * 4);
        dot = r.x * nv.x + r.y * nv.y + r.z * nv.z + r.w * nv.w;
        ss  = r.x * r.x + r.y * r.y + r.z * r.z + r.w * r.w;
    }
    #pragma unroll
    for (int o = 16; o; o >>= 1) {
        dot += __shfl_xor_sync(0xffffffffu, dot, o);
        ss  += __shfl_xor_sync(0xffffffffu, ss, o);
    }
    float w = __expf(-dot / fmaxf(sqrtf(ss), 1e-12f));
    if (lane < 26) {
        float4 s = (lane < 25)
            ? make_float4(w * r.x, w * r.y, w * r.z, w * r.w)
            : make_float4(w, 0.f, 0.f, 0.f);
        *(float4*)(g_gw[fbuf] + (size_t)node * DP + lane * 4) = s;
    }
}

// ---------------------------------------------------------------------------
// Layer 0: r = tanh(features); write out cols [0,D), build g_gw[0].
__global__ void tanh_score_kernel(const float* __restrict__ feat,
                                  float* __restrict__ out) {
    int node = (blockIdx.x * blockDim.x + threadIdx.x) >> 5;
    int lane = threadIdx.x & 31;
    if (node >= N_NODES) return;
    float4 r = make_float4(0.f, 0.f, 0.f, 0.f);
    if (lane < 25) {
        float4 v = *(const float4*)(feat + (size_t)node * D + lane * 4);
        r.x = tanha(v.x); r.y = tanha(v.y); r.z = tanha(v.z); r.w = tanha(v.w);
        *(float4*)(out + (size_t)node * OUTD + lane * 4) = r;
    }
    epilogue_store(r, lane, node, 0);
}

// ---------------------------------------------------------------------------
// Attention row kernel: gather-sum of fp32 premultiplied rows.
// 2-stage software pipeline over 4-edge batches (8 LDG.128 in flight/warp).
// Lanes 0..24 accumulate features; lane 25's first slot accumulates den.
template <bool LAST>
__global__ void __launch_bounds__(128) row_kernel(int buf, float* __restrict__ out,
                                                  int outoff) {
    int row = (blockIdx.x * blockDim.x + threadIdx.x) >> 5;
    int lane = threadIdx.x & 31;
    if (row >= N_NODES) return;
    int beg = g_rowptr[row];
    int end = g_rowptr[row + 1];
    const float* __restrict__ gwb = g_gw[buf];
    bool act = (lane < 26);
    int laneoff = lane * 4;

    u64 a0 = 0ull, a1 = 0ull, a2 = 0ull, a3 = 0ull;

    int e = beg;
    // Peel to int4-aligned coff reads.
    int pre = (4 - (beg & 3)) & 3;
    if (pre > end - beg) pre = end - beg;
    for (int k = 0; k < pre; ++k, ++e) {
        if (act) {
            ulonglong2 v = *(const ulonglong2*)(gwb + g_coff[e] + laneoff);
            fadd2(a0, v.x); fadd2(a1, v.y);
        }
    }

    if (e + 4 <= end) {
        // Pipeline stage registers: current batch (cv) / next batch (nv).
        ulonglong2 cv0, cv1, cv2, cv3;
        {
            int4 q = *(const int4*)(g_coff + e);
            if (act) {
                cv0 = *(const ulonglong2*)(gwb + q.x + laneoff);
                cv1 = *(const ulonglong2*)(gwb + q.y + laneoff);
                cv2 = *(const ulonglong2*)(gwb + q.z + laneoff);
                cv3 = *(const ulonglong2*)(gwb + q.w + laneoff);
            }
        }
        e += 4;
        for (; e + 4 <= end; e += 4) {
            int4 q = *(const int4*)(g_coff + e);
            ulonglong2 nv0, nv1, nv2, nv3;
            if (act) {
                nv0 = *(const ulonglong2*)(gwb + q.x + laneoff);
                nv1 = *(const ulonglong2*)(gwb + q.y + laneoff);
                nv2 = *(const ulonglong2*)(gwb + q.z + laneoff);
                nv3 = *(const ulonglong2*)(gwb + q.w + laneoff);
                fadd2(a0, cv0.x); fadd2(a1, cv0.y);
                fadd2(a2, cv1.x); fadd2(a3, cv1.y);
                fadd2(a0, cv2.x); fadd2(a1, cv2.y);
                fadd2(a2, cv3.x); fadd2(a3, cv3.y);
                cv0 = nv0; cv1 = nv1; cv2 = nv2; cv3 = nv3;
            }
        }
        if (act) {
            fadd2(a0, cv0.x); fadd2(a1, cv0.y);
            fadd2(a2, cv1.x); fadd2(a3, cv1.y);
            fadd2(a0, cv2.x); fadd2(a1, cv2.y);
            fadd2(a2, cv3.x); fadd2(a3, cv3.y);
        }
    }
    // Tail (<4 edges).
    for (; e < end; ++e) {
        if (act) {
            ulonglong2 v = *(const ulonglong2*)(gwb + g_coff[e] + laneoff);
            fadd2(a0, v.x); fadd2(a1, v.y);
        }
    }

    fadd2(a0, a2);
    fadd2(a1, a3);
    float2 lo = unpack2(a0);
    float2 hi = unpack2(a1);
    float den = __shfl_sync(0xffffffffu, lo.x, 25);     // lane 25 accumulated w
    float inv = (end > beg) ? (1.f / den) : 0.f;

    float4 r = make_float4(0.f, 0.f, 0.f, 0.f);
    if (lane < 25) {
        r.x = tanha(lo.x * inv);
        r.y = tanha(lo.y * inv);
        r.z = tanha(hi.x * inv);
        r.w = tanha(hi.y * inv);
        *(float4*)(out + (size_t)row * OUTD + outoff + lane * 4) = r;
    }
    if (!LAST)
        epilogue_store(r, lane, row, buf ^ 1);
}

// ---------------------------------------------------------------------------
extern "C" void kernel_launch(void* const* d_in, const int* in_sizes, int n_in,
                              void* d_out, int out_size) {
    const float* features = (const float*)d_in[0];
    // d_in[1] = rel_emb: unused by the reference computation.
    const int* adj        = (const int*)d_in[2];   // int32 pairs (JAX demotes int64)
    const float* none_rel = (const float*)d_in[3];
    float* out = (float*)d_out;

    prep_kernel<<<(E_EDGES + 255) / 256, 256>>>(adj, none_rel);
    tanh_score_kernel<<<(N_NODES * 32 + 255) / 256, 256>>>(features, out);
    const int RB = (N_NODES * 32 + 127) / 128;
    row_kernel<false><<<RB, 128>>>(0, out, D);
    row_kernel<true ><<<RB, 128>>>(1, out, 2 * D);
}